// round 16
// baseline (speedup 1.0000x reference)
#include <cuda_runtime.h>
#include <cstdint>

#define CC 512
#define CQn 64
#define HH 128
#define WW 128
#define BB 4
#define CO 640
#define NP (HH*WW)

// ---------------- scratch ----------------
__device__ __align__(256) float    g_qkv [(size_t)BB*128*NP];      // (b, o<128, h, w) tf32-rounded f32
__device__ __align__(256) float    g_qkvT[(size_t)BB*128*NP];      // (b, o<128, w, h)
__device__ __align__(256) unsigned g_xb  [(size_t)BB*256*NP];      // x bf16, pairs along channel
__device__ __align__(256) unsigned g_v   [(size_t)BB*CC*NP/2];     // (b, o, h, w) bf16 pairs along w
// v-branch AV operand: [b][t][p(h)][w][u] = bf16x2( v[8u+t](p,w), v[8u+4+t](p,w) )
__device__ __align__(256) unsigned g_vT2 [(size_t)BB*4*HH*WW*64];
__device__ __align__(256) unsigned g_ch  [(size_t)BB*HH*WW*CC/2];  // [bh][w][c] bf16
__device__ __align__(256) unsigned g_cv  [(size_t)BB*WW*HH*CC/2];  // [bw][h][c] bf16
__device__ float    g_Wqk[128*CC];
__device__ unsigned g_Wv [CC*CC/2];
__device__ float    g_ball[CO];

// ---------------- helpers ----------------
__device__ __forceinline__ float f2tff(float f) {
    unsigned u; asm("cvt.rna.tf32.f32 %0, %1;" : "=r"(u) : "f"(f)); return __uint_as_float(u);
}
__device__ __forceinline__ unsigned bf2pack(float lo, float hi) {
    unsigned r; asm("cvt.rn.bf16x2.f32 %0, %1, %2;" : "=r"(r) : "f"(hi), "f"(lo)); return r;
}
__device__ __forceinline__ void stcs_u32(unsigned* p, unsigned v) {
    asm volatile("st.global.cs.u32 [%0], %1;" :: "l"(p), "r"(v) : "memory");
}
__device__ __forceinline__ void stcs_f32(float* p, float v) {
    asm volatile("st.global.cs.f32 [%0], %1;" :: "l"(p), "f"(v) : "memory");
}
__device__ __forceinline__ void mma_tf32(float c[4], const unsigned a[4], const unsigned b[2]) {
    asm volatile("mma.sync.aligned.m16n8k8.row.col.f32.tf32.tf32.f32 "
        "{%0,%1,%2,%3}, {%4,%5,%6,%7}, {%8,%9}, {%0,%1,%2,%3};"
        : "+f"(c[0]), "+f"(c[1]), "+f"(c[2]), "+f"(c[3])
        : "r"(a[0]), "r"(a[1]), "r"(a[2]), "r"(a[3]), "r"(b[0]), "r"(b[1]));
}
__device__ __forceinline__ void mma_bf16(float c[4], const unsigned a[4], const unsigned b[2]) {
    asm volatile("mma.sync.aligned.m16n8k16.row.col.f32.bf16.bf16.f32 "
        "{%0,%1,%2,%3}, {%4,%5,%6,%7}, {%8,%9}, {%0,%1,%2,%3};"
        : "+f"(c[0]), "+f"(c[1]), "+f"(c[2]), "+f"(c[3])
        : "r"(a[0]), "r"(a[1]), "r"(a[2]), "r"(a[3]), "r"(b[0]), "r"(b[1]));
}
__device__ __forceinline__ void ldsm4(unsigned r[4], unsigned saddr) {
    asm volatile("ldmatrix.sync.aligned.m8n8.x4.shared.b16 {%0,%1,%2,%3}, [%4];"
        : "=r"(r[0]), "=r"(r[1]), "=r"(r[2]), "=r"(r[3]) : "r"(saddr));
}
__device__ __forceinline__ void cpa16(void* dst, const void* src) {
    unsigned d = (unsigned)__cvta_generic_to_shared(dst);
    asm volatile("cp.async.ca.shared.global [%0], [%1], 16;" :: "r"(d), "l"(src));
}

// ---------------- kernel 1: pack weights ----------------
__global__ void pack_kernel(const float* __restrict__ Wq, const float* __restrict__ bq,
                            const float* __restrict__ Wk, const float* __restrict__ bk,
                            const float* __restrict__ Wv, const float* __restrict__ bv) {
    int idx = blockIdx.x * blockDim.x + threadIdx.x;
    if (idx < 128 * CC) {
        int o = idx / CC, c = idx % CC;
        g_Wqk[idx] = f2tff(o < CQn ? Wq[o * CC + c] : Wk[(o - CQn) * CC + c]);
    }
    if (idx < CC * CC / 2) {
        int o = idx / (CC / 2), kp = idx % (CC / 2);
        g_Wv[idx] = bf2pack(Wv[o * CC + 2 * kp], Wv[o * CC + 2 * kp + 1]);
    }
    if (idx < CO)
        g_ball[idx] = (idx < CQn) ? bq[idx] : (idx < 2 * CQn) ? bk[idx - CQn] : bv[idx - 2 * CQn];
}

// ---------------- kernel 2a: Q/K GEMM (tf32) + x->bf16 pack side-product ----------------
__global__ __launch_bounds__(256) void qk_gemm(const float* __restrict__ x) {
    __shared__ __align__(16) float As[2][128 * 20];
    __shared__ __align__(16) float Bs[2][16 * 136];

    int n0 = blockIdx.x * 128;
    int b  = blockIdx.y;

    const float* A = g_Wqk;
    const float* B = x + (size_t)b * CC * NP;
    float*       Cp = g_qkv + (size_t)b * 128 * NP;
    unsigned*    xb = g_xb + (size_t)b * 256 * NP;

    int tid = threadIdx.x;
    int wid = tid >> 5, lane = tid & 31;
    int wm = wid >> 1, wn = wid & 1;
    int g = lane >> 2, tc = lane & 3;

    int arow = tid >> 2, acol = (tid & 3) * 4;
    int brow = tid >> 5, bcol = lane * 4;

    float acc[2][8][4];
    #pragma unroll
    for (int mf = 0; mf < 2; mf++)
        #pragma unroll
        for (int nf = 0; nf < 8; nf++)
            #pragma unroll
            for (int r = 0; r < 4; r++) acc[mf][nf][r] = 0.f;

    #pragma unroll
    for (int h = 0; h < 2; h++) {
        cpa16(&As[0][(arow + h * 64) * 20 + acol], &A[(size_t)(arow + h * 64) * CC + acol]);
        cpa16(&Bs[0][(brow + h * 8) * 136 + bcol], &B[(size_t)(brow + h * 8) * NP + n0 + bcol]);
    }
    asm volatile("cp.async.commit_group;");
    asm volatile("cp.async.wait_group 0;");
    __syncthreads();

    for (int k0 = 0; k0 < CC; k0 += 16) {
        int buf = (k0 >> 4) & 1;
        if (k0 + 16 < CC) {
            #pragma unroll
            for (int h = 0; h < 2; h++) {
                cpa16(&As[buf ^ 1][(arow + h * 64) * 20 + acol],
                      &A[(size_t)(arow + h * 64) * CC + k0 + 16 + acol]);
                cpa16(&Bs[buf ^ 1][(brow + h * 8) * 136 + bcol],
                      &B[(size_t)(k0 + 16 + brow + h * 8) * NP + n0 + bcol]);
            }
            asm volatile("cp.async.commit_group;");
        }
        const unsigned* Asu = (const unsigned*)As[buf];
        const unsigned* Bsu = (const unsigned*)Bs[buf];
        #pragma unroll
        for (int ks = 0; ks < 16; ks += 8) {
            unsigned af[2][4];
            #pragma unroll
            for (int mf = 0; mf < 2; mf++) {
                int r0 = wm * 32 + mf * 16 + g;
                af[mf][0] = Asu[(r0    ) * 20 + ks + tc];
                af[mf][1] = Asu[(r0 + 8) * 20 + ks + tc];
                af[mf][2] = Asu[(r0    ) * 20 + ks + tc + 4];
                af[mf][3] = Asu[(r0 + 8) * 20 + ks + tc + 4];
            }
            unsigned bfv[8][2];
            #pragma unroll
            for (int nf = 0; nf < 8; nf++) {
                int nn = wn * 64 + nf * 8 + g;
                bfv[nf][0] = Bsu[(ks + tc    ) * 136 + nn];
                bfv[nf][1] = Bsu[(ks + tc + 4) * 136 + nn];
            }
            #pragma unroll
            for (int mf = 0; mf < 2; mf++)
                #pragma unroll
                for (int nf = 0; nf < 8; nf++)
                    mma_tf32(acc[mf][nf], af[mf], bfv[nf]);
        }
        // side-product: pack this x tile to bf16 (pairs along channel)
        #pragma unroll
        for (int i = 0; i < 4; i++) {
            int idx = tid + i * 256;
            int kpl = idx >> 7, n = idx & 127;
            float f0 = Bs[buf][(2 * kpl) * 136 + n];
            float f1 = Bs[buf][(2 * kpl + 1) * 136 + n];
            xb[(size_t)((k0 >> 1) + kpl) * NP + n0 + n] = bf2pack(f0, f1);
        }
        if (k0 + 16 < CC) asm volatile("cp.async.wait_group 0;");
        __syncthreads();
    }

    #pragma unroll
    for (int mf = 0; mf < 2; mf++) {
        int i0 = wm * 32 + mf * 16 + g;
        float bv0 = g_ball[i0], bv1 = g_ball[i0 + 8];
        #pragma unroll
        for (int nf = 0; nf < 8; nf++) {
            int j = n0 + wn * 64 + nf * 8 + 2 * tc;
            float2 w0 = {f2tff(acc[mf][nf][0] + bv0), f2tff(acc[mf][nf][1] + bv0)};
            float2 w1 = {f2tff(acc[mf][nf][2] + bv1), f2tff(acc[mf][nf][3] + bv1)};
            *reinterpret_cast<float2*>(&Cp[(size_t)i0 * NP + j])       = w0;
            *reinterpret_cast<float2*>(&Cp[(size_t)(i0 + 8) * NP + j]) = w1;
        }
    }
}

// ---------------- kernel 2b: V GEMM + backfilled qk-transpose ----------------
// blocks [0,2048): V GEMM (bf16 m16n8k16, ldmatrix; B from g_xb)
//   vb = bid: mx = vb&3, ny = (vb>>2)&127, bz = vb>>9
// blocks [2048,10240): 32x32 f32 transpose tiles of g_qkv -> g_qkvT (fills v_gemm idle slots)
__global__ __launch_bounds__(256) void v_gemm_plus() {
    __shared__ __align__(16) unsigned smraw[4 * 2560];   // 40 KB, aliased by both paths

    int bid = blockIdx.x;
    int tid = threadIdx.x;

    if (bid >= 2048) {
        // ---- qk transpose tile ----
        float (*t)[33] = (float(*)[33])smraw;
        int tb = bid - 2048;
        int plane = tb >> 4;
        int w0 = ((tb >> 2) & 3) * 32, h0 = (tb & 3) * 32;
        const float* src = g_qkv + (size_t)plane * NP;
        float*       dst = g_qkvT + (size_t)plane * NP;
        int tx = tid & 31, ty = tid >> 5;
        #pragma unroll
        for (int r = 0; r < 32; r += 8)
            t[ty + r][tx] = src[(size_t)(h0 + ty + r) * WW + w0 + tx];
        __syncthreads();
        #pragma unroll
        for (int r = 0; r < 32; r += 8)
            dst[(size_t)(w0 + ty + r) * HH + h0 + tx] = t[tx][ty + r];
        return;
    }

    // ---- V GEMM ----
    unsigned* AsB[2] = { smraw,            smraw + 2560 };
    unsigned* BsB[2] = { smraw + 5120,     smraw + 7680 };

    int m0 = (bid & 3) * 128;
    int n0 = ((bid >> 2) & 127) * 128;
    int b  = bid >> 9;

    const unsigned* A  = g_Wv;
    const unsigned* Xb = g_xb + (size_t)b * 256 * NP;
    unsigned*       vp = g_v + (size_t)b * CC * (NP / 2);

    int wid = tid >> 5, lane = tid & 31;
    int wm = wid >> 1, wn = wid & 1;
    int g = lane >> 2, tc = lane & 3;

    int ar = tid >> 1, ac = (tid & 1) * 8;
    int ku0 = (wid & 3) * 4, nbase = 64 * (wid >> 2);

    int lrow = lane & 15;
    int lhi  = (lane >> 4) << 2;
    unsigned aadr[2][2], badr[2][4];
    #pragma unroll
    for (int bfi = 0; bfi < 2; bfi++) {
        #pragma unroll
        for (int mf = 0; mf < 2; mf++)
            aadr[bfi][mf] = (unsigned)__cvta_generic_to_shared(
                &AsB[bfi][(wm * 32 + mf * 16 + lrow) * 20 + lhi]);
        #pragma unroll
        for (int ng = 0; ng < 4; ng++)
            badr[bfi][ng] = (unsigned)__cvta_generic_to_shared(
                &BsB[bfi][(wn * 64 + ng * 16 + lrow) * 20 + lhi]);
    }

    unsigned pB[2][4];
    #pragma unroll
    for (int r = 0; r < 2; r++) {
        int n = nbase + 32 * r + lane;
        #pragma unroll
        for (int d = 0; d < 4; d++)
            pB[r][d] = Xb[(size_t)(ku0 + d) * NP + n0 + n];
    }
    #pragma unroll
    for (int c = 0; c < 2; c++)
        cpa16(&AsB[0][ar * 20 + ac + 4 * c], &A[(size_t)(m0 + ar) * 256 + ac + 4 * c]);
    asm volatile("cp.async.commit_group;");
    #pragma unroll
    for (int r = 0; r < 2; r++) {
        int n = nbase + 32 * r + lane;
        *reinterpret_cast<uint4*>(&BsB[0][n * 20 + ku0]) = *reinterpret_cast<uint4*>(pB[r]);
    }
    asm volatile("cp.async.wait_group 0;");
    __syncthreads();

    float acc[2][8][4];
    #pragma unroll
    for (int mf = 0; mf < 2; mf++)
        #pragma unroll
        for (int nf = 0; nf < 8; nf++)
            #pragma unroll
            for (int r = 0; r < 4; r++) acc[mf][nf][r] = 0.f;

    for (int kt = 0; kt < 16; kt++) {
        int buf = kt & 1;
        if (kt < 15) {
            #pragma unroll
            for (int c = 0; c < 2; c++)
                cpa16(&AsB[buf ^ 1][ar * 20 + ac + 4 * c],
                      &A[(size_t)(m0 + ar) * 256 + (kt + 1) * 16 + ac + 4 * c]);
            asm volatile("cp.async.commit_group;");
            #pragma unroll
            for (int r = 0; r < 2; r++) {
                int n = nbase + 32 * r + lane;
                #pragma unroll
                for (int d = 0; d < 4; d++)
                    pB[r][d] = Xb[(size_t)((kt + 1) * 16 + ku0 + d) * NP + n0 + n];
            }
        }

        #pragma unroll
        for (int s = 0; s < 2; s++) {
            unsigned koff = s * 32;
            unsigned aA[2][4], bB[4][4];
            ldsm4(aA[0], aadr[buf][0] + koff);
            ldsm4(aA[1], aadr[buf][1] + koff);
            #pragma unroll
            for (int ng = 0; ng < 4; ng++) ldsm4(bB[ng], badr[buf][ng] + koff);
            #pragma unroll
            for (int mf = 0; mf < 2; mf++)
                #pragma unroll
                for (int nf = 0; nf < 8; nf++) {
                    int ng = nf >> 1, hf = nf & 1;
                    unsigned b2[2] = { bB[ng][hf], bB[ng][hf + 2] };
                    mma_bf16(acc[mf][nf], aA[mf], b2);
                }
        }

        if (kt < 15) {
            #pragma unroll
            for (int r = 0; r < 2; r++) {
                int n = nbase + 32 * r + lane;
                *reinterpret_cast<uint4*>(&BsB[buf ^ 1][n * 20 + ku0]) = *reinterpret_cast<uint4*>(pB[r]);
            }
            asm volatile("cp.async.wait_group 0;");
        }
        __syncthreads();
    }

    #pragma unroll
    for (int mf = 0; mf < 2; mf++) {
        int i0 = m0 + wm * 32 + mf * 16 + g;
        float bv0 = g_ball[128 + i0], bv1 = g_ball[128 + i0 + 8];
        #pragma unroll
        for (int nf = 0; nf < 8; nf++) {
            int j = n0 + wn * 64 + nf * 8 + 2 * tc;
            vp[(size_t)i0 * (NP / 2) + (j >> 1)]       = bf2pack(acc[mf][nf][0] + bv0, acc[mf][nf][1] + bv0);
            vp[(size_t)(i0 + 8) * (NP / 2) + (j >> 1)] = bf2pack(acc[mf][nf][2] + bv1, acc[mf][nf][3] + bv1);
        }
    }
}

// ---------------- kernel 3: build g_vT2 (v-branch AV operand layout) ----------------
__global__ __launch_bounds__(256) void transpose_v2() {
    __shared__ unsigned lo[64 * 65];
    __shared__ unsigned hi[64 * 65];
    int bid2 = blockIdx.x;
    int h = bid2 & 127, t = (bid2 >> 7) & 3, b = bid2 >> 9;
    const unsigned* src = g_v + (size_t)b * CC * (NP / 2);

    for (int e = threadIdx.x; e < 4096; e += 256) {
        int u = e >> 6, w2 = e & 63;
        lo[u * 65 + w2] = src[((size_t)(8 * u + t)     * 128 + h) * 64 + w2];
        hi[u * 65 + w2] = src[((size_t)(8 * u + 4 + t) * 128 + h) * 64 + w2];
    }
    __syncthreads();

    unsigned* dst = g_vT2 + ((size_t)(b * 4 + t) * 128 + h) * 8192;
    for (int e = threadIdx.x; e < 8192; e += 256) {
        int w = e >> 6, u = e & 63;
        unsigned a = lo[u * 65 + (w >> 1)], bb = hi[u * 65 + (w >> 1)];
        dst[(size_t)w * 64 + u] = (w & 1) ? __byte_perm(a, bb, 0x7632)
                                          : __byte_perm(a, bb, 0x5410);
    }
}

// =============== attention machinery (512 threads, 16 warps, 2 CTA/SM) ===============

__device__ __forceinline__ void issue_vchunk(unsigned* dst, const unsigned* vrow, int mc, int tid) {
    #pragma unroll
    for (int k = 0; k < 4; k++) {
        int lin = k * 512 + tid;
        int ml = lin >> 4, seg = lin & 15;
        cpa16(&dst[ml * 68 + seg * 4], vrow + (size_t)(mc + ml) * (NP / 2) + seg * 4);
    }
}

template<int AKMAJOR>
__device__ __forceinline__ void energy_softmax(const unsigned* aA, const unsigned* kbu,
                                               unsigned* ebu, float2* pm, int wid, int lane,
                                               unsigned* vb0, unsigned* vb1,
                                               const unsigned* vrow, int tid) {
    int wr8 = wid >> 1, wc2 = wid & 1;
    int ib = wr8 * 16, jb = wc2 * 64, jb2 = wc2 * 32;
    int g = lane >> 2, tc = lane & 3;

    float acc[8][4];
    #pragma unroll
    for (int nf = 0; nf < 8; nf++)
        #pragma unroll
        for (int r = 0; r < 4; r++) acc[nf][r] = 0.f;

    for (int a0 = 0; a0 < 64; a0 += 8) {
        unsigned af[4];
        if (AKMAJOR) {
            af[0] = aA[(a0 + tc    ) * 136 + ib + g];
            af[1] = aA[(a0 + tc    ) * 136 + ib + g + 8];
            af[2] = aA[(a0 + tc + 4) * 136 + ib + g];
            af[3] = aA[(a0 + tc + 4) * 136 + ib + g + 8];
        } else {
            af[0] = aA[(ib + g    ) * 68 + a0 + tc];
            af[1] = aA[(ib + g + 8) * 68 + a0 + tc];
            af[2] = aA[(ib + g    ) * 68 + a0 + tc + 4];
            af[3] = aA[(ib + g + 8) * 68 + a0 + tc + 4];
        }
        #pragma unroll
        for (int nf = 0; nf < 8; nf++) {
            int j = jb + nf * 8 + g;
            unsigned bfr[2] = { kbu[j * 68 + a0 + tc], kbu[j * 68 + a0 + tc + 4] };
            mma_tf32(acc[nf], af, bfr);
        }
    }

    float mx0 = -1e30f, mx1 = -1e30f;
    #pragma unroll
    for (int nf = 0; nf < 8; nf++) {
        mx0 = fmaxf(mx0, fmaxf(acc[nf][0], acc[nf][1]));
        mx1 = fmaxf(mx1, fmaxf(acc[nf][2], acc[nf][3]));
    }
    mx0 = fmaxf(mx0, __shfl_xor_sync(0xffffffffu, mx0, 1));
    mx0 = fmaxf(mx0, __shfl_xor_sync(0xffffffffu, mx0, 2));
    mx1 = fmaxf(mx1, __shfl_xor_sync(0xffffffffu, mx1, 1));
    mx1 = fmaxf(mx1, __shfl_xor_sync(0xffffffffu, mx1, 2));
    float s0 = 0.f, s1 = 0.f;
    #pragma unroll
    for (int nf = 0; nf < 8; nf++) {
        acc[nf][0] = __expf(acc[nf][0] - mx0); s0 += acc[nf][0];
        acc[nf][1] = __expf(acc[nf][1] - mx0); s0 += acc[nf][1];
        acc[nf][2] = __expf(acc[nf][2] - mx1); s1 += acc[nf][2];
        acc[nf][3] = __expf(acc[nf][3] - mx1); s1 += acc[nf][3];
    }
    s0 += __shfl_xor_sync(0xffffffffu, s0, 1);
    s0 += __shfl_xor_sync(0xffffffffu, s0, 2);
    s1 += __shfl_xor_sync(0xffffffffu, s1, 1);
    s1 += __shfl_xor_sync(0xffffffffu, s1, 2);

    int row0 = ib + g, row1 = row0 + 8;
    if (tc == 0) {
        pm[row0 * 2 + wc2] = make_float2(mx0, s0);
        pm[row1 * 2 + wc2] = make_float2(mx1, s1);
    }
    __syncthreads();

    issue_vchunk(vb0, vrow, 0, tid);
    asm volatile("cp.async.commit_group;");
    issue_vchunk(vb1, vrow, 128, tid);
    asm volatile("cp.async.commit_group;");

    float2 q0 = pm[row0 * 2 + (wc2 ^ 1)];
    float2 q1 = pm[row1 * 2 + (wc2 ^ 1)];
    float M0 = fmaxf(mx0, q0.x);
    float M1 = fmaxf(mx1, q1.x);
    float f0 = __expf(mx0 - M0) / (s0 * __expf(mx0 - M0) + q0.y * __expf(q0.x - M0));
    float f1 = __expf(mx1 - M1) / (s1 * __expf(mx1 - M1) + q1.y * __expf(q1.x - M1));

    #pragma unroll
    for (int nf = 0; nf < 8; nf++) {
        ebu[row0 * 68 + jb2 + nf * 4 + tc] = bf2pack(acc[nf][0] * f0, acc[nf][1] * f0);
        ebu[row1 * 68 + jb2 + nf * 4 + tc] = bf2pack(acc[nf][2] * f1, acc[nf][3] * f1);
    }
}

__device__ __forceinline__ void av_mma(const unsigned* ebu, const unsigned* vbu,
                                       unsigned* outu, int mglob0, int ib, int mb,
                                       int lane, int g, int tc) {
    int lrow = lane & 15;
    int lhi  = (lane >> 4) << 2;
    unsigned aadr[2], badr[2];
    #pragma unroll
    for (int mf = 0; mf < 2; mf++)
        aadr[mf] = (unsigned)__cvta_generic_to_shared(&ebu[(ib + mf * 16 + lrow) * 68 + lhi]);
    #pragma unroll
    for (int ng = 0; ng < 2; ng++)
        badr[ng] = (unsigned)__cvta_generic_to_shared(&vbu[(mb + ng * 16 + lrow) * 68 + lhi]);

    float acc[2][4][4];
    #pragma unroll
    for (int mf = 0; mf < 2; mf++)
        #pragma unroll
        for (int nf = 0; nf < 4; nf++)
            #pragma unroll
            for (int r = 0; r < 4; r++) acc[mf][nf][r] = 0.f;

    #pragma unroll
    for (int j0 = 0; j0 < 128; j0 += 16) {
        unsigned koff = (unsigned)(j0 * 2);
        unsigned aA[2][4], bB[2][4];
        ldsm4(aA[0], aadr[0] + koff);
        ldsm4(aA[1], aadr[1] + koff);
        ldsm4(bB[0], badr[0] + koff);
        ldsm4(bB[1], badr[1] + koff);
        #pragma unroll
        for (int mf = 0; mf < 2; mf++)
            #pragma unroll
            for (int nf = 0; nf < 4; nf++) {
                int ng = nf >> 1, hf = nf & 1;
                unsigned b2[2] = { bB[ng][hf], bB[ng][hf + 2] };
                mma_bf16(acc[mf][nf], aA[mf], b2);
            }
    }
    #pragma unroll
    for (int mf = 0; mf < 2; mf++) {
        int i = ib + mf * 16 + g;
        #pragma unroll
        for (int nf = 0; nf < 4; nf++) {
            int m = mglob0 + mb + nf * 8 + 2 * tc;
            stcs_u32(&outu[(size_t)i * (CC / 2) + (m >> 1)],
                     bf2pack(acc[mf][nf][0], acc[mf][nf][1]));
            stcs_u32(&outu[(size_t)(i + 8) * (CC / 2) + (m >> 1)],
                     bf2pack(acc[mf][nf][2], acc[mf][nf][3]));
        }
    }
}

// ---------------- kernel 4: merged attention (blocks 0..511 = h, 512..1023 = v) ----------------
__global__ __launch_bounds__(512, 2) void attn() {
    extern __shared__ unsigned smu[];
    int tid = threadIdx.x;
    int wid = tid >> 5, lane = tid & 31;
    int g = lane >> 2, tc = lane & 3;

    unsigned* vb0 = smu;
    unsigned* vb1 = smu + 8704;
    unsigned* ebu = smu + 17408;
    float2*   pm  = (float2*)(smu + 26112);

    const unsigned* vrow;
    unsigned* outu;

    if (blockIdx.x < 512) {
        int bh = blockIdx.x;
        int b = bh >> 7, h = bh & 127;
        vrow = g_v + (size_t)b * CC * (NP / 2) + h * (WW / 2);
        outu = g_ch + (size_t)bh * WW * (CC / 2);

        float* qs = (float*)smu;            // [a][i] stride 136
        float* kb = (float*)(smu + 8704);   // [j][a] stride 68
        const float* qbase = g_qkv + (size_t)b * 128 * NP + h * WW;
        const float* kbase = qbase + (size_t)64 * NP;
        for (int idx = tid * 4; idx < CQn * WW; idx += 2048) {
            int a = idx >> 7, i = idx & 127;
            cpa16(&qs[a * 136 + i], &qbase[(size_t)a * NP + i]);
        }
        asm volatile("cp.async.commit_group;");
        for (int idx = tid; idx < CQn * WW; idx += 512) {
            int c2 = idx >> 7, w2 = idx & 127;
            kb[(((w2 & 1) << 6) + c2) * 68 + (w2 >> 1)] = kbase[(size_t)c2 * NP + w2];
        }
        asm volatile("cp.async.wait_group 0;");
        __syncthreads();
        energy_softmax<1>((const unsigned*)qs, (const unsigned*)kb, ebu, pm, wid, lane,
                          vb0, vb1, vrow, tid);
    } else {
        int bw = blockIdx.x - 512;
        int b = bw >> 7, w = bw & 127;
        vrow = g_vT2 + (size_t)b * 4 * 1048576 + w * 64;
        outu = g_cv + (size_t)bw * HH * (CC / 2);

        float* aq = (float*)smu;            // [i][a] stride 68
        float* kb = (float*)(smu + 8704);   // [j][a] stride 68
        const float* qbaseT = g_qkvT + (size_t)b * 128 * NP + w * HH;
        const float* kbaseT = qbaseT + (size_t)64 * NP;
        for (int idx = tid * 4; idx < HH * CQn; idx += 2048) {
            int i = idx >> 6, a = idx & 63;
            cpa16(&aq[i * 68 + a], &qbaseT[(size_t)(i >> 1) * NP + ((i & 1) << 6) + a]);
        }
        asm volatile("cp.async.commit_group;");
        for (int idx = tid; idx < CQn * HH; idx += 512) {
            int a = idx >> 7, j = idx & 127;
            kb[j * 68 + a] = kbaseT[(size_t)a * NP + j];
        }
        asm volatile("cp.async.wait_group 0;");
        __syncthreads();
        energy_softmax<0>((const unsigned*)aq, (const unsigned*)kb, ebu, pm, wid, lane,
                          vb0, vb1, vrow, tid);
    }
    __syncthreads();

    int ib4 = (wid >> 2) * 32, mb4 = (wid & 3) * 32;
    for (int c = 0; c < 4; c++) {
        if (c == 3) asm volatile("cp.async.wait_group 0;");
        else        asm volatile("cp.async.wait_group 1;");
        __syncthreads();
        av_mma(ebu, (c & 1) ? vb1 : vb0, outu, c * 128, ib4, mb4, lane, g, tc);
        __syncthreads();
        if (c < 2) {
            issue_vchunk((c & 1) ? vb1 : vb0, vrow, (c + 2) * 128, tid);
            asm volatile("cp.async.commit_group;");
        }
    }
}

// ---------------- kernel 5: combine ----------------
__global__ __launch_bounds__(256) void combine_kernel(const float* __restrict__ x,
                                                      const float* __restrict__ gamma,
                                                      float* __restrict__ out) {
    __shared__ float tb[32][67];
    int w0 = blockIdx.x * 32;
    int c0 = blockIdx.y * 64;
    int bh = blockIdx.z;
    int b = bh >> 7, h = bh & 127;
    int tx = threadIdx.x, ty = threadIdx.y;

    for (int r = ty; r < 32; r += 8) {
        int w = w0 + r;
        unsigned chp = g_ch[((size_t)bh * WW + w) * (CC / 2) + (c0 >> 1) + tx];
        unsigned cvp = g_cv[(((size_t)(b * WW + w)) * HH + h) * (CC / 2) + (c0 >> 1) + tx];
        float lo = __uint_as_float(chp << 16) + __uint_as_float(cvp << 16);
        float hi = __uint_as_float(chp & 0xffff0000u) + __uint_as_float(cvp & 0xffff0000u);
        tb[r][2 * tx]     = lo;
        tb[r][2 * tx + 1] = hi;
    }
    __syncthreads();
    float gv = gamma[0];
    for (int rr = ty; rr < 64; rr += 8) {
        int c = c0 + rr;
        size_t o = ((size_t)(b * CC + c) * HH + h) * WW + w0 + tx;
        stcs_f32(&out[o], gv * tb[tx][rr] + x[o]);
    }
}

// ---------------- launch (single stream) ----------------
extern "C" void kernel_launch(void* const* d_in, const int* in_sizes, int n_in,
                              void* d_out, int out_size) {
    const float* x     = (const float*)d_in[0];
    const float* Wq    = (const float*)d_in[1];
    const float* bq    = (const float*)d_in[2];
    const float* Wk    = (const float*)d_in[3];
    const float* bk    = (const float*)d_in[4];
    const float* Wv    = (const float*)d_in[5];
    const float* bv    = (const float*)d_in[6];
    const float* gamma = (const float*)d_in[7];
    float* out = (float*)d_out;

    const int ASM = 26624 * 4;   // 106496 B -> 2 CTAs/SM
    cudaFuncSetAttribute(attn, cudaFuncAttributeMaxDynamicSharedMemorySize, ASM);

    pack_kernel<<<(CC * CC / 2 + 255) / 256, 256>>>(Wq, bq, Wk, bk, Wv, bv);
    qk_gemm<<<dim3(128, 4), 256>>>(x);
    v_gemm_plus<<<2048 + 8192, 256>>>();
    transpose_v2<<<2048, 256>>>();
    attn<<<1024, 512, ASM>>>();
    combine_kernel<<<dim3(WW / 32, CC / 64, BB * HH), dim3(32, 8, 1)>>>(x, gamma, out);
}

// round 17
// speedup vs baseline: 1.0535x; 1.0535x over previous
#include <cuda_runtime.h>
#include <cstdint>

#define CC 512
#define CQn 64
#define HH 128
#define WW 128
#define BB 4
#define CO 640
#define NP (HH*WW)

// ---------------- scratch ----------------
__device__ __align__(256) float    g_qkv [(size_t)BB*128*NP];      // (b, o<128, h, w) tf32-rounded f32
__device__ __align__(256) float    g_qkvT[(size_t)BB*128*NP];      // (b, o<128, w, h)
__device__ __align__(256) unsigned g_xb  [(size_t)BB*256*NP];      // x bf16, pairs along channel
__device__ __align__(256) unsigned g_v   [(size_t)BB*CC*NP/2];     // (b, o, h, w) bf16 pairs along w
// v-branch AV operand: [b][t][p(h)][w][u] = bf16x2( v[8u+t](p,w), v[8u+4+t](p,w) )
__device__ __align__(256) unsigned g_vT2 [(size_t)BB*4*HH*WW*64];
__device__ __align__(256) unsigned g_ch  [(size_t)BB*HH*WW*CC/2];  // [bh][w][c] bf16
__device__ __align__(256) unsigned g_cv  [(size_t)BB*WW*HH*CC/2];  // [bw][h][c] bf16
__device__ float    g_Wqk[128*CC];
__device__ unsigned g_Wv [CC*CC/2];
__device__ float    g_ball[CO];

// ---------------- helpers ----------------
__device__ __forceinline__ float f2tff(float f) {
    unsigned u; asm("cvt.rna.tf32.f32 %0, %1;" : "=r"(u) : "f"(f)); return __uint_as_float(u);
}
__device__ __forceinline__ unsigned bf2pack(float lo, float hi) {
    unsigned r; asm("cvt.rn.bf16x2.f32 %0, %1, %2;" : "=r"(r) : "f"(hi), "f"(lo)); return r;
}
__device__ __forceinline__ void stcs_u32(unsigned* p, unsigned v) {
    asm volatile("st.global.cs.u32 [%0], %1;" :: "l"(p), "r"(v) : "memory");
}
__device__ __forceinline__ void stcs_f32(float* p, float v) {
    asm volatile("st.global.cs.f32 [%0], %1;" :: "l"(p), "f"(v) : "memory");
}
__device__ __forceinline__ void mma_tf32(float c[4], const unsigned a[4], const unsigned b[2]) {
    asm volatile("mma.sync.aligned.m16n8k8.row.col.f32.tf32.tf32.f32 "
        "{%0,%1,%2,%3}, {%4,%5,%6,%7}, {%8,%9}, {%0,%1,%2,%3};"
        : "+f"(c[0]), "+f"(c[1]), "+f"(c[2]), "+f"(c[3])
        : "r"(a[0]), "r"(a[1]), "r"(a[2]), "r"(a[3]), "r"(b[0]), "r"(b[1]));
}
__device__ __forceinline__ void mma_bf16(float c[4], const unsigned a[4], const unsigned b[2]) {
    asm volatile("mma.sync.aligned.m16n8k16.row.col.f32.bf16.bf16.f32 "
        "{%0,%1,%2,%3}, {%4,%5,%6,%7}, {%8,%9}, {%0,%1,%2,%3};"
        : "+f"(c[0]), "+f"(c[1]), "+f"(c[2]), "+f"(c[3])
        : "r"(a[0]), "r"(a[1]), "r"(a[2]), "r"(a[3]), "r"(b[0]), "r"(b[1]));
}
__device__ __forceinline__ void ldsm4(unsigned r[4], unsigned saddr) {
    asm volatile("ldmatrix.sync.aligned.m8n8.x4.shared.b16 {%0,%1,%2,%3}, [%4];"
        : "=r"(r[0]), "=r"(r[1]), "=r"(r[2]), "=r"(r[3]) : "r"(saddr));
}
__device__ __forceinline__ void cpa16(void* dst, const void* src) {
    unsigned d = (unsigned)__cvta_generic_to_shared(dst);
    asm volatile("cp.async.ca.shared.global [%0], [%1], 16;" :: "r"(d), "l"(src));
}

// ---------------- kernel 1: pack weights ----------------
__global__ void pack_kernel(const float* __restrict__ Wq, const float* __restrict__ bq,
                            const float* __restrict__ Wk, const float* __restrict__ bk,
                            const float* __restrict__ Wv, const float* __restrict__ bv) {
    int idx = blockIdx.x * blockDim.x + threadIdx.x;
    if (idx < 128 * CC) {
        int o = idx / CC, c = idx % CC;
        g_Wqk[idx] = f2tff(o < CQn ? Wq[o * CC + c] : Wk[(o - CQn) * CC + c]);
    }
    if (idx < CC * CC / 2) {
        int o = idx / (CC / 2), kp = idx % (CC / 2);
        g_Wv[idx] = bf2pack(Wv[o * CC + 2 * kp], Wv[o * CC + 2 * kp + 1]);
    }
    if (idx < CO)
        g_ball[idx] = (idx < CQn) ? bq[idx] : (idx < 2 * CQn) ? bk[idx - CQn] : bv[idx - 2 * CQn];
}

// ---------------- kernel 2a: Q/K GEMM (tf32) + x->bf16 pack side-product ----------------
__global__ __launch_bounds__(256) void qk_gemm(const float* __restrict__ x) {
    __shared__ __align__(16) float As[2][128 * 20];
    __shared__ __align__(16) float Bs[2][16 * 136];

    int n0 = blockIdx.x * 128;
    int b  = blockIdx.y;

    const float* A = g_Wqk;
    const float* B = x + (size_t)b * CC * NP;
    float*       Cp = g_qkv + (size_t)b * 128 * NP;
    unsigned*    xb = g_xb + (size_t)b * 256 * NP;

    int tid = threadIdx.x;
    int wid = tid >> 5, lane = tid & 31;
    int wm = wid >> 1, wn = wid & 1;
    int g = lane >> 2, tc = lane & 3;

    int arow = tid >> 2, acol = (tid & 3) * 4;
    int brow = tid >> 5, bcol = lane * 4;

    float acc[2][8][4];
    #pragma unroll
    for (int mf = 0; mf < 2; mf++)
        #pragma unroll
        for (int nf = 0; nf < 8; nf++)
            #pragma unroll
            for (int r = 0; r < 4; r++) acc[mf][nf][r] = 0.f;

    #pragma unroll
    for (int h = 0; h < 2; h++) {
        cpa16(&As[0][(arow + h * 64) * 20 + acol], &A[(size_t)(arow + h * 64) * CC + acol]);
        cpa16(&Bs[0][(brow + h * 8) * 136 + bcol], &B[(size_t)(brow + h * 8) * NP + n0 + bcol]);
    }
    asm volatile("cp.async.commit_group;");
    asm volatile("cp.async.wait_group 0;");
    __syncthreads();

    for (int k0 = 0; k0 < CC; k0 += 16) {
        int buf = (k0 >> 4) & 1;
        if (k0 + 16 < CC) {
            #pragma unroll
            for (int h = 0; h < 2; h++) {
                cpa16(&As[buf ^ 1][(arow + h * 64) * 20 + acol],
                      &A[(size_t)(arow + h * 64) * CC + k0 + 16 + acol]);
                cpa16(&Bs[buf ^ 1][(brow + h * 8) * 136 + bcol],
                      &B[(size_t)(k0 + 16 + brow + h * 8) * NP + n0 + bcol]);
            }
            asm volatile("cp.async.commit_group;");
        }
        const unsigned* Asu = (const unsigned*)As[buf];
        const unsigned* Bsu = (const unsigned*)Bs[buf];
        #pragma unroll
        for (int ks = 0; ks < 16; ks += 8) {
            unsigned af[2][4];
            #pragma unroll
            for (int mf = 0; mf < 2; mf++) {
                int r0 = wm * 32 + mf * 16 + g;
                af[mf][0] = Asu[(r0    ) * 20 + ks + tc];
                af[mf][1] = Asu[(r0 + 8) * 20 + ks + tc];
                af[mf][2] = Asu[(r0    ) * 20 + ks + tc + 4];
                af[mf][3] = Asu[(r0 + 8) * 20 + ks + tc + 4];
            }
            unsigned bfv[8][2];
            #pragma unroll
            for (int nf = 0; nf < 8; nf++) {
                int nn = wn * 64 + nf * 8 + g;
                bfv[nf][0] = Bsu[(ks + tc    ) * 136 + nn];
                bfv[nf][1] = Bsu[(ks + tc + 4) * 136 + nn];
            }
            #pragma unroll
            for (int mf = 0; mf < 2; mf++)
                #pragma unroll
                for (int nf = 0; nf < 8; nf++)
                    mma_tf32(acc[mf][nf], af[mf], bfv[nf]);
        }
        // side-product: pack this x tile to bf16 (pairs along channel)
        #pragma unroll
        for (int i = 0; i < 4; i++) {
            int idx = tid + i * 256;
            int kpl = idx >> 7, n = idx & 127;
            float f0 = Bs[buf][(2 * kpl) * 136 + n];
            float f1 = Bs[buf][(2 * kpl + 1) * 136 + n];
            xb[(size_t)((k0 >> 1) + kpl) * NP + n0 + n] = bf2pack(f0, f1);
        }
        if (k0 + 16 < CC) asm volatile("cp.async.wait_group 0;");
        __syncthreads();
    }

    #pragma unroll
    for (int mf = 0; mf < 2; mf++) {
        int i0 = wm * 32 + mf * 16 + g;
        float bv0 = g_ball[i0], bv1 = g_ball[i0 + 8];
        #pragma unroll
        for (int nf = 0; nf < 8; nf++) {
            int j = n0 + wn * 64 + nf * 8 + 2 * tc;
            float2 w0 = {f2tff(acc[mf][nf][0] + bv0), f2tff(acc[mf][nf][1] + bv0)};
            float2 w1 = {f2tff(acc[mf][nf][2] + bv1), f2tff(acc[mf][nf][3] + bv1)};
            *reinterpret_cast<float2*>(&Cp[(size_t)i0 * NP + j])       = w0;
            *reinterpret_cast<float2*>(&Cp[(size_t)(i0 + 8) * NP + j]) = w1;
        }
    }
}

// ---------------- kernel 2b: V GEMM (bf16 m16n8k16, ldmatrix; B from g_xb) ----------------
__global__ __launch_bounds__(256) void v_gemm() {
    __shared__ __align__(16) unsigned As[2][128 * 20];
    __shared__ __align__(16) unsigned Bs[2][128 * 20];

    int m0 = blockIdx.x * 128;
    int n0 = blockIdx.y * 128;
    int b  = blockIdx.z;

    const unsigned* A  = g_Wv;
    const unsigned* Xb = g_xb + (size_t)b * 256 * NP;
    unsigned*       vp = g_v + (size_t)b * CC * (NP / 2);

    int tid = threadIdx.x;
    int wid = tid >> 5, lane = tid & 31;
    int wm = wid >> 1, wn = wid & 1;
    int g = lane >> 2, tc = lane & 3;

    int ar = tid >> 1, ac = (tid & 1) * 8;
    int ku0 = (wid & 3) * 4, nbase = 64 * (wid >> 2);

    int lrow = lane & 15;
    int lhi  = (lane >> 4) << 2;
    unsigned aadr[2][2], badr[2][4];
    #pragma unroll
    for (int bfi = 0; bfi < 2; bfi++) {
        #pragma unroll
        for (int mf = 0; mf < 2; mf++)
            aadr[bfi][mf] = (unsigned)__cvta_generic_to_shared(
                &As[bfi][(wm * 32 + mf * 16 + lrow) * 20 + lhi]);
        #pragma unroll
        for (int ng = 0; ng < 4; ng++)
            badr[bfi][ng] = (unsigned)__cvta_generic_to_shared(
                &Bs[bfi][(wn * 64 + ng * 16 + lrow) * 20 + lhi]);
    }

    unsigned pB[2][4];
    #pragma unroll
    for (int r = 0; r < 2; r++) {
        int n = nbase + 32 * r + lane;
        #pragma unroll
        for (int d = 0; d < 4; d++)
            pB[r][d] = Xb[(size_t)(ku0 + d) * NP + n0 + n];
    }
    #pragma unroll
    for (int c = 0; c < 2; c++)
        cpa16(&As[0][ar * 20 + ac + 4 * c], &A[(size_t)(m0 + ar) * 256 + ac + 4 * c]);
    asm volatile("cp.async.commit_group;");
    #pragma unroll
    for (int r = 0; r < 2; r++) {
        int n = nbase + 32 * r + lane;
        *reinterpret_cast<uint4*>(&Bs[0][n * 20 + ku0]) = *reinterpret_cast<uint4*>(pB[r]);
    }
    asm volatile("cp.async.wait_group 0;");
    __syncthreads();

    float acc[2][8][4];
    #pragma unroll
    for (int mf = 0; mf < 2; mf++)
        #pragma unroll
        for (int nf = 0; nf < 8; nf++)
            #pragma unroll
            for (int r = 0; r < 4; r++) acc[mf][nf][r] = 0.f;

    for (int kt = 0; kt < 16; kt++) {
        int buf = kt & 1;
        if (kt < 15) {
            #pragma unroll
            for (int c = 0; c < 2; c++)
                cpa16(&As[buf ^ 1][ar * 20 + ac + 4 * c],
                      &A[(size_t)(m0 + ar) * 256 + (kt + 1) * 16 + ac + 4 * c]);
            asm volatile("cp.async.commit_group;");
            #pragma unroll
            for (int r = 0; r < 2; r++) {
                int n = nbase + 32 * r + lane;
                #pragma unroll
                for (int d = 0; d < 4; d++)
                    pB[r][d] = Xb[(size_t)((kt + 1) * 16 + ku0 + d) * NP + n0 + n];
            }
        }

        #pragma unroll
        for (int s = 0; s < 2; s++) {
            unsigned koff = s * 32;
            unsigned aA[2][4], bB[4][4];
            ldsm4(aA[0], aadr[buf][0] + koff);
            ldsm4(aA[1], aadr[buf][1] + koff);
            #pragma unroll
            for (int ng = 0; ng < 4; ng++) ldsm4(bB[ng], badr[buf][ng] + koff);
            #pragma unroll
            for (int mf = 0; mf < 2; mf++)
                #pragma unroll
                for (int nf = 0; nf < 8; nf++) {
                    int ng = nf >> 1, hf = nf & 1;
                    unsigned b2[2] = { bB[ng][hf], bB[ng][hf + 2] };
                    mma_bf16(acc[mf][nf], aA[mf], b2);
                }
        }

        if (kt < 15) {
            #pragma unroll
            for (int r = 0; r < 2; r++) {
                int n = nbase + 32 * r + lane;
                *reinterpret_cast<uint4*>(&Bs[buf ^ 1][n * 20 + ku0]) = *reinterpret_cast<uint4*>(pB[r]);
            }
            asm volatile("cp.async.wait_group 0;");
        }
        __syncthreads();
    }

    #pragma unroll
    for (int mf = 0; mf < 2; mf++) {
        int i0 = m0 + wm * 32 + mf * 16 + g;
        float bv0 = g_ball[128 + i0], bv1 = g_ball[128 + i0 + 8];
        #pragma unroll
        for (int nf = 0; nf < 8; nf++) {
            int j = n0 + wn * 64 + nf * 8 + 2 * tc;
            vp[(size_t)i0 * (NP / 2) + (j >> 1)]       = bf2pack(acc[mf][nf][0] + bv0, acc[mf][nf][1] + bv0);
            vp[(size_t)(i0 + 8) * (NP / 2) + (j >> 1)] = bf2pack(acc[mf][nf][2] + bv1, acc[mf][nf][3] + bv1);
        }
    }
}

// ---------------- kernel 3: merged transposes ----------------
__global__ __launch_bounds__(256) void transpose_all() {
    int bid = blockIdx.x;
    if (bid < 8192) {
        __shared__ float t[32][33];
        int plane = bid >> 4;
        int w0 = ((bid >> 2) & 3) * 32, h0 = (bid & 3) * 32;
        const float* src = g_qkv + (size_t)plane * NP;
        float*       dst = g_qkvT + (size_t)plane * NP;
        int tx = threadIdx.x & 31, ty = threadIdx.x >> 5;
        #pragma unroll
        for (int r = 0; r < 32; r += 8)
            t[ty + r][tx] = src[(size_t)(h0 + ty + r) * WW + w0 + tx];
        __syncthreads();
        #pragma unroll
        for (int r = 0; r < 32; r += 8)
            dst[(size_t)(w0 + ty + r) * HH + h0 + tx] = t[tx][ty + r];
    } else {
        __shared__ unsigned lo[64 * 65];
        __shared__ unsigned hi[64 * 65];
        int bid2 = bid - 8192;
        int h = bid2 & 127, t = (bid2 >> 7) & 3, b = bid2 >> 9;
        const unsigned* src = g_v + (size_t)b * CC * (NP / 2);

        for (int e = threadIdx.x; e < 4096; e += 256) {
            int u = e >> 6, w2 = e & 63;
            lo[u * 65 + w2] = src[((size_t)(8 * u + t)     * 128 + h) * 64 + w2];
            hi[u * 65 + w2] = src[((size_t)(8 * u + 4 + t) * 128 + h) * 64 + w2];
        }
        __syncthreads();

        unsigned* dst = g_vT2 + ((size_t)(b * 4 + t) * 128 + h) * 8192;
        for (int e = threadIdx.x; e < 8192; e += 256) {
            int w = e >> 6, u = e & 63;
            unsigned a = lo[u * 65 + (w >> 1)], bb = hi[u * 65 + (w >> 1)];
            dst[(size_t)w * 64 + u] = (w & 1) ? __byte_perm(a, bb, 0x7632)
                                              : __byte_perm(a, bb, 0x5410);
        }
    }
}

// =============== attention machinery (512 threads, 16 warps, 2 CTA/SM) ===============

__device__ __forceinline__ void issue_vchunk(unsigned* dst, const unsigned* vrow, int mc, int tid) {
    #pragma unroll
    for (int k = 0; k < 4; k++) {
        int lin = k * 512 + tid;
        int ml = lin >> 4, seg = lin & 15;
        cpa16(&dst[ml * 68 + seg * 4], vrow + (size_t)(mc + ml) * (NP / 2) + seg * 4);
    }
}

template<int AKMAJOR>
__device__ __forceinline__ void energy_softmax(const unsigned* aA, const unsigned* kbu,
                                               unsigned* ebu, float2* pm, int wid, int lane,
                                               unsigned* vb0, unsigned* vb1,
                                               const unsigned* vrow, int tid) {
    int wr8 = wid >> 1, wc2 = wid & 1;
    int ib = wr8 * 16, jb = wc2 * 64, jb2 = wc2 * 32;
    int g = lane >> 2, tc = lane & 3;

    float acc[8][4];
    #pragma unroll
    for (int nf = 0; nf < 8; nf++)
        #pragma unroll
        for (int r = 0; r < 4; r++) acc[nf][r] = 0.f;

    for (int a0 = 0; a0 < 64; a0 += 8) {
        unsigned af[4];
        if (AKMAJOR) {
            af[0] = aA[(a0 + tc    ) * 136 + ib + g];
            af[1] = aA[(a0 + tc    ) * 136 + ib + g + 8];
            af[2] = aA[(a0 + tc + 4) * 136 + ib + g];
            af[3] = aA[(a0 + tc + 4) * 136 + ib + g + 8];
        } else {
            af[0] = aA[(ib + g    ) * 68 + a0 + tc];
            af[1] = aA[(ib + g + 8) * 68 + a0 + tc];
            af[2] = aA[(ib + g    ) * 68 + a0 + tc + 4];
            af[3] = aA[(ib + g + 8) * 68 + a0 + tc + 4];
        }
        #pragma unroll
        for (int nf = 0; nf < 8; nf++) {
            int j = jb + nf * 8 + g;
            unsigned bfr[2] = { kbu[j * 68 + a0 + tc], kbu[j * 68 + a0 + tc + 4] };
            mma_tf32(acc[nf], af, bfr);
        }
    }

    float mx0 = -1e30f, mx1 = -1e30f;
    #pragma unroll
    for (int nf = 0; nf < 8; nf++) {
        mx0 = fmaxf(mx0, fmaxf(acc[nf][0], acc[nf][1]));
        mx1 = fmaxf(mx1, fmaxf(acc[nf][2], acc[nf][3]));
    }
    mx0 = fmaxf(mx0, __shfl_xor_sync(0xffffffffu, mx0, 1));
    mx0 = fmaxf(mx0, __shfl_xor_sync(0xffffffffu, mx0, 2));
    mx1 = fmaxf(mx1, __shfl_xor_sync(0xffffffffu, mx1, 1));
    mx1 = fmaxf(mx1, __shfl_xor_sync(0xffffffffu, mx1, 2));
    float s0 = 0.f, s1 = 0.f;
    #pragma unroll
    for (int nf = 0; nf < 8; nf++) {
        acc[nf][0] = __expf(acc[nf][0] - mx0); s0 += acc[nf][0];
        acc[nf][1] = __expf(acc[nf][1] - mx0); s0 += acc[nf][1];
        acc[nf][2] = __expf(acc[nf][2] - mx1); s1 += acc[nf][2];
        acc[nf][3] = __expf(acc[nf][3] - mx1); s1 += acc[nf][3];
    }
    s0 += __shfl_xor_sync(0xffffffffu, s0, 1);
    s0 += __shfl_xor_sync(0xffffffffu, s0, 2);
    s1 += __shfl_xor_sync(0xffffffffu, s1, 1);
    s1 += __shfl_xor_sync(0xffffffffu, s1, 2);

    int row0 = ib + g, row1 = row0 + 8;
    if (tc == 0) {
        pm[row0 * 2 + wc2] = make_float2(mx0, s0);
        pm[row1 * 2 + wc2] = make_float2(mx1, s1);
    }
    __syncthreads();

    issue_vchunk(vb0, vrow, 0, tid);
    asm volatile("cp.async.commit_group;");
    issue_vchunk(vb1, vrow, 128, tid);
    asm volatile("cp.async.commit_group;");

    float2 q0 = pm[row0 * 2 + (wc2 ^ 1)];
    float2 q1 = pm[row1 * 2 + (wc2 ^ 1)];
    float M0 = fmaxf(mx0, q0.x);
    float M1 = fmaxf(mx1, q1.x);
    float f0 = __expf(mx0 - M0) / (s0 * __expf(mx0 - M0) + q0.y * __expf(q0.x - M0));
    float f1 = __expf(mx1 - M1) / (s1 * __expf(mx1 - M1) + q1.y * __expf(q1.x - M1));

    #pragma unroll
    for (int nf = 0; nf < 8; nf++) {
        ebu[row0 * 68 + jb2 + nf * 4 + tc] = bf2pack(acc[nf][0] * f0, acc[nf][1] * f0);
        ebu[row1 * 68 + jb2 + nf * 4 + tc] = bf2pack(acc[nf][2] * f1, acc[nf][3] * f1);
    }
}

__device__ __forceinline__ void av_mma(const unsigned* ebu, const unsigned* vbu,
                                       unsigned* outu, int mglob0, int ib, int mb,
                                       int lane, int g, int tc) {
    int lrow = lane & 15;
    int lhi  = (lane >> 4) << 2;
    unsigned aadr[2], badr[2];
    #pragma unroll
    for (int mf = 0; mf < 2; mf++)
        aadr[mf] = (unsigned)__cvta_generic_to_shared(&ebu[(ib + mf * 16 + lrow) * 68 + lhi]);
    #pragma unroll
    for (int ng = 0; ng < 2; ng++)
        badr[ng] = (unsigned)__cvta_generic_to_shared(&vbu[(mb + ng * 16 + lrow) * 68 + lhi]);

    float acc[2][4][4];
    #pragma unroll
    for (int mf = 0; mf < 2; mf++)
        #pragma unroll
        for (int nf = 0; nf < 4; nf++)
            #pragma unroll
            for (int r = 0; r < 4; r++) acc[mf][nf][r] = 0.f;

    #pragma unroll
    for (int j0 = 0; j0 < 128; j0 += 16) {
        unsigned koff = (unsigned)(j0 * 2);
        unsigned aA[2][4], bB[2][4];
        ldsm4(aA[0], aadr[0] + koff);
        ldsm4(aA[1], aadr[1] + koff);
        ldsm4(bB[0], badr[0] + koff);
        ldsm4(bB[1], badr[1] + koff);
        #pragma unroll
        for (int mf = 0; mf < 2; mf++)
            #pragma unroll
            for (int nf = 0; nf < 4; nf++) {
                int ng = nf >> 1, hf = nf & 1;
                unsigned b2[2] = { bB[ng][hf], bB[ng][hf + 2] };
                mma_bf16(acc[mf][nf], aA[mf], b2);
            }
    }
    #pragma unroll
    for (int mf = 0; mf < 2; mf++) {
        int i = ib + mf * 16 + g;
        #pragma unroll
        for (int nf = 0; nf < 4; nf++) {
            int m = mglob0 + mb + nf * 8 + 2 * tc;
            stcs_u32(&outu[(size_t)i * (CC / 2) + (m >> 1)],
                     bf2pack(acc[mf][nf][0], acc[mf][nf][1]));
            stcs_u32(&outu[(size_t)(i + 8) * (CC / 2) + (m >> 1)],
                     bf2pack(acc[mf][nf][2], acc[mf][nf][3]));
        }
    }
}

// ---------------- kernel 4: merged attention (blocks 0..511 = h, 512..1023 = v) ----------------
__global__ __launch_bounds__(512, 2) void attn() {
    extern __shared__ unsigned smu[];
    int tid = threadIdx.x;
    int wid = tid >> 5, lane = tid & 31;
    int g = lane >> 2, tc = lane & 3;

    unsigned* vb0 = smu;
    unsigned* vb1 = smu + 8704;
    unsigned* ebu = smu + 17408;
    float2*   pm  = (float2*)(smu + 26112);

    const unsigned* vrow;
    unsigned* outu;

    if (blockIdx.x < 512) {
        int bh = blockIdx.x;
        int b = bh >> 7, h = bh & 127;
        vrow = g_v + (size_t)b * CC * (NP / 2) + h * (WW / 2);
        outu = g_ch + (size_t)bh * WW * (CC / 2);

        float* qs = (float*)smu;            // [a][i] stride 136
        float* kb = (float*)(smu + 8704);   // [j][a] stride 68
        const float* qbase = g_qkv + (size_t)b * 128 * NP + h * WW;
        const float* kbase = qbase + (size_t)64 * NP;
        for (int idx = tid * 4; idx < CQn * WW; idx += 2048) {
            int a = idx >> 7, i = idx & 127;
            cpa16(&qs[a * 136 + i], &qbase[(size_t)a * NP + i]);
        }
        asm volatile("cp.async.commit_group;");
        for (int idx = tid; idx < CQn * WW; idx += 512) {
            int c2 = idx >> 7, w2 = idx & 127;
            kb[(((w2 & 1) << 6) + c2) * 68 + (w2 >> 1)] = kbase[(size_t)c2 * NP + w2];
        }
        asm volatile("cp.async.wait_group 0;");
        __syncthreads();
        energy_softmax<1>((const unsigned*)qs, (const unsigned*)kb, ebu, pm, wid, lane,
                          vb0, vb1, vrow, tid);
    } else {
        int bw = blockIdx.x - 512;
        int b = bw >> 7, w = bw & 127;
        vrow = g_vT2 + (size_t)b * 4 * 1048576 + w * 64;
        outu = g_cv + (size_t)bw * HH * (CC / 2);

        float* aq = (float*)smu;            // [i][a] stride 68
        float* kb = (float*)(smu + 8704);   // [j][a] stride 68
        const float* qbaseT = g_qkvT + (size_t)b * 128 * NP + w * HH;
        const float* kbaseT = qbaseT + (size_t)64 * NP;
        for (int idx = tid * 4; idx < HH * CQn; idx += 2048) {
            int i = idx >> 6, a = idx & 63;
            cpa16(&aq[i * 68 + a], &qbaseT[(size_t)(i >> 1) * NP + ((i & 1) << 6) + a]);
        }
        asm volatile("cp.async.commit_group;");
        for (int idx = tid; idx < CQn * HH; idx += 512) {
            int a = idx >> 7, j = idx & 127;
            kb[j * 68 + a] = kbaseT[(size_t)a * NP + j];
        }
        asm volatile("cp.async.wait_group 0;");
        __syncthreads();
        energy_softmax<0>((const unsigned*)aq, (const unsigned*)kb, ebu, pm, wid, lane,
                          vb0, vb1, vrow, tid);
    }
    __syncthreads();

    int ib4 = (wid >> 2) * 32, mb4 = (wid & 3) * 32;
    for (int c = 0; c < 4; c++) {
        if (c == 3) asm volatile("cp.async.wait_group 0;");
        else        asm volatile("cp.async.wait_group 1;");
        __syncthreads();
        av_mma(ebu, (c & 1) ? vb1 : vb0, outu, c * 128, ib4, mb4, lane, g, tc);
        __syncthreads();
        if (c < 2) {
            issue_vchunk((c & 1) ? vb1 : vb0, vrow, (c + 2) * 128, tid);
            asm volatile("cp.async.commit_group;");
        }
    }
}

// ---------------- kernel 5: combine ----------------
__global__ __launch_bounds__(256) void combine_kernel(const float* __restrict__ x,
                                                      const float* __restrict__ gamma,
                                                      float* __restrict__ out) {
    __shared__ float tb[32][67];
    int w0 = blockIdx.x * 32;
    int c0 = blockIdx.y * 64;
    int bh = blockIdx.z;
    int b = bh >> 7, h = bh & 127;
    int tx = threadIdx.x, ty = threadIdx.y;

    for (int r = ty; r < 32; r += 8) {
        int w = w0 + r;
        unsigned chp = g_ch[((size_t)bh * WW + w) * (CC / 2) + (c0 >> 1) + tx];
        unsigned cvp = g_cv[(((size_t)(b * WW + w)) * HH + h) * (CC / 2) + (c0 >> 1) + tx];
        float lo = __uint_as_float(chp << 16) + __uint_as_float(cvp << 16);
        float hi = __uint_as_float(chp & 0xffff0000u) + __uint_as_float(cvp & 0xffff0000u);
        tb[r][2 * tx]     = lo;
        tb[r][2 * tx + 1] = hi;
    }
    __syncthreads();
    float gv = gamma[0];
    for (int rr = ty; rr < 64; rr += 8) {
        int c = c0 + rr;
        size_t o = ((size_t)(b * CC + c) * HH + h) * WW + w0 + tx;
        stcs_f32(&out[o], gv * tb[tx][rr] + x[o]);
    }
}

// ---------------- launch (single stream) ----------------
extern "C" void kernel_launch(void* const* d_in, const int* in_sizes, int n_in,
                              void* d_out, int out_size) {
    const float* x     = (const float*)d_in[0];
    const float* Wq    = (const float*)d_in[1];
    const float* bq    = (const float*)d_in[2];
    const float* Wk    = (const float*)d_in[3];
    const float* bk    = (const float*)d_in[4];
    const float* Wv    = (const float*)d_in[5];
    const float* bv    = (const float*)d_in[6];
    const float* gamma = (const float*)d_in[7];
    float* out = (float*)d_out;

    const int ASM = 26624 * 4;   // 106496 B -> 2 CTAs/SM
    cudaFuncSetAttribute(attn, cudaFuncAttributeMaxDynamicSharedMemorySize, ASM);

    pack_kernel<<<(CC * CC / 2 + 255) / 256, 256>>>(Wq, bq, Wk, bk, Wv, bv);
    qk_gemm<<<dim3(128, 4), 256>>>(x);
    v_gemm<<<dim3(4, 128, 4), 256>>>();
    transpose_all<<<8192 + 2048, 256>>>();
    attn<<<1024, 512, ASM>>>();
    combine_kernel<<<dim3(WW / 32, CC / 64, BB * HH), dim3(32, 8, 1)>>>(x, gamma, out);
}